// round 8
// baseline (speedup 1.0000x reference)
#include <cuda_runtime.h>
#include <math.h>

#define TPB 256
#define MAXK 128
#define QCAP 1024

// Per-block partials: [(b*gx+bx)*4 + {stc,str,cnt,pad}]. Every used slot is
// written each run, so no zeroing kernel is needed.
__device__ float g_part[65536];
// Wrap-around completion counter: returns to 0 after every full run, so graph
// replays are deterministic without an init kernel.
__device__ unsigned g_ctr = 0;

#define C4 0.2857142857f      /* 0.4/1.4 */

__device__ __forceinline__ float softplusf(float z) {
    return fmaxf(z, 0.f) + __logf(1.f + __expf(-fabsf(z)));
}

template<int KFIX>
__global__ __launch_bounds__(TPB) void loss_kernel(
    const float* __restrict__ prop,     // (B, A, 6)
    const float* __restrict__ anchors,  // (A, 4) xywh
    const float* __restrict__ gt,       // (B, K, 4) xywh
    float* __restrict__ out,
    int A, int Krt, int perBlock, int totalBlocks)
{
    const int K = (KFIX > 0) ? KFIX : Krt;
    __shared__ float4 s_g[MAXK];          // gt boxes xyxy
    __shared__ float  s_ga[MAXK];         // gt areas
    __shared__ float  s_g4[MAXK];         // (2/7)*ga
    __shared__ int    s_q[QCAP];          // candidate anchor ids
    __shared__ int    s_qc;
    __shared__ float  r0[8], r1[8], r2[8];
    __shared__ int    s_last;
    __shared__ float  s_fin[8][4];

    const int b  = blockIdx.y;
    const int gx = gridDim.x;

    if (threadIdx.x == 0) s_qc = 0;
    for (int k = threadIdx.x; k < K; k += TPB) {
        const float* g = gt + ((size_t)b * K + k) * 4;
        float x0 = g[0], y0 = g[1], w = g[2], h = g[3];
        s_g[k]  = make_float4(x0, y0, x0 + w, y0 + h);
        float ga = w * h;
        s_ga[k] = ga;
        s_g4[k] = C4 * ga;
    }
    __syncthreads();

    const int start = blockIdx.x * perBlock;
    const int end   = min(start + perBlock, A);

    float stc = 0.f, strl = 0.f, cnt = 0.f;

    // -------- screen phases over this block's contiguous anchor range -------
    // Screen invariant: M4 = max_k( inter_k - (2/7)*ga_k )
    //   neg  <=> M4 <  (2/7)*areaA      (max iou < 0.4)
    //   cand <=> M4 >= 0.3330*areaA     (superset of pos: pos => M4 >= areaA/3 + ga/21)
    // inter = max(w,0)*h: h<0 makes the term negative, harmless under max.
    int base = start;
    while (base + TPB < end) {
        // paired phase: two anchors per thread, shared LDS, ILP-2
        const int a0 = base + threadIdx.x;
        const int a1 = a0 + TPB;
        const int c0 = min(a0, end - 1);
        const int c1 = min(a1, end - 1);

        const float4 an0 = reinterpret_cast<const float4*>(anchors)[c0];
        const float4 an1 = reinterpret_cast<const float4*>(anchors)[c1];
        const float xl0 = __ldg(prop + ((size_t)b * A + c0) * 6 + 4);
        const float xl1 = __ldg(prop + ((size_t)b * A + c1) * 6 + 4);

        const float ax1_0 = an0.x, ay1_0 = an0.y;
        const float ax2_0 = an0.x + an0.z, ay2_0 = an0.y + an0.w;
        const float areaA0 = an0.z * an0.w;
        const float ax1_1 = an1.x, ay1_1 = an1.y;
        const float ax2_1 = an1.x + an1.z, ay2_1 = an1.y + an1.w;
        const float areaA1 = an1.z * an1.w;

        float M0 = -1e30f, M1 = -1e30f;
#pragma unroll 4
        for (int k = 0; k < K; k++) {
            float4 g = s_g[k];
            float g4 = s_g4[k];
            {
                float w = fminf(ax2_0, g.z) - fmaxf(ax1_0, g.x);
                float h = fminf(ay2_0, g.w) - fmaxf(ay1_0, g.y);
                M0 = fmaxf(M0, fmaf(fmaxf(w, 0.f), h, -g4));
            }
            {
                float w = fminf(ax2_1, g.z) - fmaxf(ax1_1, g.x);
                float h = fminf(ay2_1, g.w) - fmaxf(ay1_1, g.y);
                M1 = fmaxf(M1, fmaf(fmaxf(w, 0.f), h, -g4));
            }
        }
        if (a0 < end) {
            if (M0 < C4 * areaA0) {
                float sig = 1.f / (1.f + __expf(-xl0));
                stc += 0.75f * softplusf(xl0) * sig * sig;
            } else if (M0 >= 0.3330f * areaA0) {
                s_q[atomicAdd(&s_qc, 1)] = a0;
            }
        }
        if (a1 < end) {
            if (M1 < C4 * areaA1) {
                float sig = 1.f / (1.f + __expf(-xl1));
                stc += 0.75f * softplusf(xl1) * sig * sig;
            } else if (M1 >= 0.3330f * areaA1) {
                s_q[atomicAdd(&s_qc, 1)] = a1;
            }
        }
        base += 2 * TPB;
    }
    if (base < end) {
        // remainder phase: single anchor, only low warps active
        const int a0 = base + threadIdx.x;
        if (a0 < end) {
            const float4 an0 = reinterpret_cast<const float4*>(anchors)[a0];
            const float xl0 = __ldg(prop + ((size_t)b * A + a0) * 6 + 4);
            const float ax1_0 = an0.x, ay1_0 = an0.y;
            const float ax2_0 = an0.x + an0.z, ay2_0 = an0.y + an0.w;
            const float areaA0 = an0.z * an0.w;
            float M0 = -1e30f;
#pragma unroll 4
            for (int k = 0; k < K; k++) {
                float4 g = s_g[k];
                float g4 = s_g4[k];
                float w = fminf(ax2_0, g.z) - fmaxf(ax1_0, g.x);
                float h = fminf(ay2_0, g.w) - fmaxf(ay1_0, g.y);
                M0 = fmaxf(M0, fmaf(fmaxf(w, 0.f), h, -g4));
            }
            if (M0 < C4 * areaA0) {
                float sig = 1.f / (1.f + __expf(-xl0));
                stc += 0.75f * softplusf(xl0) * sig * sig;
            } else if (M0 >= 0.3330f * areaA0) {
                s_q[atomicAdd(&s_qc, 1)] = a0;
            }
        }
    }
    __syncthreads();

    // ---- pass-2: exact classification + argmax for candidates (dense) ----
    const int qc = s_qc;
    for (int i = threadIdx.x; i < qc; i += TPB) {
        const int a = s_q[i];
        const float4 an = reinterpret_cast<const float4*>(anchors)[a];
        const float ax1 = an.x, ay1 = an.y;
        const float ax2 = an.x + an.z, ay2 = an.y + an.w;
        const float areaA = an.z * an.w;

        // division-free exact argmax (strict > keeps first max) — verified
        // bitwise against reference path (rel_err 6.6e-8)
        float bI = 0.f, bS = 1.f; int bK = 0;
        for (int k = 0; k < K; k++) {
            float4 g = s_g[k];
            float w = fminf(ax2, g.z) - fmaxf(ax1, g.x);
            float h = fminf(ay2, g.w) - fmaxf(ay1, g.y);
            float inter = fmaxf(w, 0.f) * h;
            float S = areaA + s_ga[k];
            bool c = inter * bS > bI * S;
            bI = c ? inter : bI;
            bS = c ? S : bS;
            bK = c ? k : bK;
        }
        const float ts = bI / (bS - bI);

        const float* p = prop + ((size_t)b * A + a) * 6;
        const float x = p[4];
        const float sig = 1.f / (1.f + __expf(-x));
        if (ts >= 0.5f) {
            cnt += 1.f;
            float om = 1.f - sig;
            stc += 0.25f * softplusf(-x) * om * om;         // focal, t=1
            float2 q01 = *reinterpret_cast<const float2*>(p);
            float2 q23 = *reinterpret_cast<const float2*>(p + 2);
            float4 g = s_g[bK];
            float ew = fmaxf(fminf(q01.x + q23.x, g.z) - fmaxf(q01.x, g.x), 0.f);
            float eh = fmaxf(fminf(q01.y + q23.y, g.w) - fmaxf(q01.y, g.y), 0.f);
            float ei = ew * eh;
            float eiou = ei / ((q23.x * q23.y + s_ga[bK]) - ei);
            strl += -__logf(eiou + 0.01f);
        } else if (ts < 0.4f) {
            stc += 0.75f * softplusf(x) * sig * sig;        // focal, t=0
        }
    }

    // ---- block reduction of (stc, strl, cnt) ----
    const unsigned m = 0xFFFFFFFFu;
#pragma unroll
    for (int o = 16; o; o >>= 1) {
        stc  += __shfl_down_sync(m, stc,  o);
        strl += __shfl_down_sync(m, strl, o);
        cnt  += __shfl_down_sync(m, cnt,  o);
    }
    const int wid = threadIdx.x >> 5, lane = threadIdx.x & 31;
    if (lane == 0) { r0[wid] = stc; r1[wid] = strl; r2[wid] = cnt; }
    __syncthreads();
    if (threadIdx.x == 0) {
        float t0 = 0.f, t1 = 0.f, t2 = 0.f;
#pragma unroll
        for (int i = 0; i < TPB / 32; i++) { t0 += r0[i]; t1 += r1[i]; t2 += r2[i]; }
        int slot = (b * gx + blockIdx.x) * 4;
        g_part[slot + 0] = t0;
        g_part[slot + 1] = t1;
        g_part[slot + 2] = t2;
        __threadfence();
        unsigned old = atomicInc(&g_ctr, (unsigned)(totalBlocks - 1));
        s_last = (old == (unsigned)(totalBlocks - 1)) ? 1 : 0;
    }
    __syncthreads();

    if (s_last) {
        const int B = gridDim.y;
        const int nwarp = TPB / 32;
        if (threadIdx.x < 32) ((float*)s_fin)[threadIdx.x] = 0.f;
        __syncthreads();

        if (B <= nwarp) {
            const int wpb = nwarp / B;            // warps per batch
            const int bb = wid / wpb;
            if (bb < B) {
                float f0 = 0.f, f1 = 0.f, f2 = 0.f;
                for (int blk = lane + 32 * (wid % wpb); blk < gx; blk += 32 * wpb) {
                    int s = (bb * gx + blk) * 4;
                    f0 += g_part[s + 0];
                    f1 += g_part[s + 1];
                    f2 += g_part[s + 2];
                }
#pragma unroll
                for (int o = 16; o; o >>= 1) {
                    f0 += __shfl_down_sync(m, f0, o);
                    f1 += __shfl_down_sync(m, f1, o);
                    f2 += __shfl_down_sync(m, f2, o);
                }
                if (lane == 0) {
                    atomicAdd(&s_fin[bb][0], f0);
                    atomicAdd(&s_fin[bb][1], f1);
                    atomicAdd(&s_fin[bb][2], f2);
                }
            }
            __syncthreads();
            if (threadIdx.x == 0) {
                float t = 0.f;
                for (int bb2 = 0; bb2 < B; bb2++) {
                    float c = s_fin[bb2][2];
                    float safe = (c > 0.f) ? c : 1.f;
                    t += s_fin[bb2][0] / safe;
                    if (c > 0.f) t += s_fin[bb2][1] / safe;
                }
                out[0] = t / (float)B;
            }
        } else if (threadIdx.x == 0) {
            // fallback (B > nwarp): serial, correctness only
            float t = 0.f;
            for (int bb2 = 0; bb2 < B; bb2++) {
                float f0 = 0.f, f1 = 0.f, f2 = 0.f;
                for (int blk = 0; blk < gx; blk++) {
                    int s = (bb2 * gx + blk) * 4;
                    f0 += g_part[s]; f1 += g_part[s + 1]; f2 += g_part[s + 2];
                }
                float safe = (f2 > 0.f) ? f2 : 1.f;
                t += f0 / safe;
                if (f2 > 0.f) t += f1 / safe;
            }
            out[0] = t / (float)B;
        }
    }
}

extern "C" void kernel_launch(void* const* d_in, const int* in_sizes, int n_in,
                              void* d_out, int out_size) {
    const float* prop    = (const float*)d_in[0];  // ss_proposal (B,A,6)
    const float* anchors = (const float*)d_in[1];  // anchors (A,4)
    const float* gt      = (const float*)d_in[2];  // ground_truth (B,K,4)

    const int A = in_sizes[1] / 4;
    const int B = in_sizes[0] / (A * 6);
    const int K = in_sizes[2] / (B * 4);

    // Single-wave geometry: gx*B = 148 SMs * 5 blocks/SM. For B=4: gx=185,
    // perBlock=649. Cap perBlock at QCAP (queue capacity).
    int gx = (148 * 5) / B;
    if (gx < 1) gx = 1;
    int perBlock = (A + gx - 1) / gx;
    if (perBlock > QCAP) {
        perBlock = QCAP;
        gx = (A + perBlock - 1) / perBlock;
    }
    dim3 grid(gx, B);
    const int total = gx * B;

    if (K == 64)
        loss_kernel<64><<<grid, TPB>>>(prop, anchors, gt, (float*)d_out, A, K, perBlock, total);
    else
        loss_kernel<0><<<grid, TPB>>>(prop, anchors, gt, (float*)d_out, A, K, perBlock, total);
}

// round 9
// speedup vs baseline: 1.0653x; 1.0653x over previous
#include <cuda_runtime.h>
#include <math.h>

#define TPB 256
#define MAXK 128
#define QCAP 288

// Per-block partials: [(b*gx+bx)*4 + {stc,str,cnt,pad}]. Every used slot is
// written each run, so no zeroing kernel is needed.
__device__ float g_part[65536];
// Wrap-around completion counter: returns to 0 after every full run, so graph
// replays are deterministic without an init kernel.
__device__ unsigned g_ctr = 0;

#define C4 0.2857142857f      /* 0.4/1.4 */

__device__ __forceinline__ float softplusf(float z) {
    return fmaxf(z, 0.f) + __logf(1.f + __expf(-fabsf(z)));
}

template<int KFIX>
__global__ __launch_bounds__(TPB) void loss_kernel(
    const float* __restrict__ prop,     // (B, A, 6)
    const float* __restrict__ anchors,  // (A, 4) xywh
    const float* __restrict__ gt,       // (B, K, 4) xywh
    float* __restrict__ out,
    int A, int Krt, int totalBlocks)
{
    const int K = (KFIX > 0) ? KFIX : Krt;
    __shared__ float4 s_g[MAXK];          // gt boxes xyxy
    __shared__ float  s_ga[MAXK];         // gt areas
    __shared__ float4 s_g4v[MAXK / 4];    // (2/7)*ga, packed 4-per-float4
    __shared__ int    s_q[QCAP];          // candidate anchor ids
    __shared__ int    s_qc;
    __shared__ float  r0[8], r1[8], r2[8];
    __shared__ int    s_last;
    __shared__ float  s_fin[8][4];

    const int b  = blockIdx.y;
    const int gx = gridDim.x;

    if (threadIdx.x == 0) s_qc = 0;
    for (int k = threadIdx.x; k < K; k += TPB) {
        const float* g = gt + ((size_t)b * K + k) * 4;
        float x0 = g[0], y0 = g[1], w = g[2], h = g[3];
        s_g[k]  = make_float4(x0, y0, x0 + w, y0 + h);
        float ga = w * h;
        s_ga[k] = ga;
        ((float*)s_g4v)[k] = C4 * ga;
    }
    __syncthreads();

    // ---- one anchor per thread: minimal state, max resident warps ----
    const int a = blockIdx.x * TPB + threadIdx.x;
    const int c = min(a, A - 1);

    const float4 an = reinterpret_cast<const float4*>(anchors)[c];
    const float xl  = __ldg(prop + ((size_t)b * A + c) * 6 + 4);  // logit, prefetched

    const float ax1 = an.x, ay1 = an.y;
    const float ax2 = an.x + an.z, ay2 = an.y + an.w;
    const float areaA = an.z * an.w;

    // Screen: M4 = max_k( inter_k - (2/7)*ga_k ).  (exact in real arithmetic:)
    //   max iou >= 0.4  <=>  M4 >= (2/7)*areaA
    //   pos (max iou >= 0.5) ==> M4 >= areaA/3 + ga*/21 > 0.3330*areaA (margin)
    // inter = max(w,0)*h: h<0 gives a negative term, harmless under max.
    float M4 = -1e30f;

    if (KFIX == 64) {
#pragma unroll
        for (int k4 = 0; k4 < 16; k4++) {
            float4 gv = s_g4v[k4];
#pragma unroll
            for (int i = 0; i < 4; i++) {
                float4 g = s_g[k4 * 4 + i];
                float g4 = (i == 0) ? gv.x : (i == 1) ? gv.y : (i == 2) ? gv.z : gv.w;
                float w = fminf(ax2, g.z) - fmaxf(ax1, g.x);
                float h = fminf(ay2, g.w) - fmaxf(ay1, g.y);
                M4 = fmaxf(M4, fmaf(fmaxf(w, 0.f), h, -g4));
            }
        }
    } else {
        for (int k = 0; k < K; k++) {
            float4 g = s_g[k];
            float g4 = ((const float*)s_g4v)[k];
            float w = fminf(ax2, g.z) - fmaxf(ax1, g.x);
            float h = fminf(ay2, g.w) - fmaxf(ay1, g.y);
            M4 = fmaxf(M4, fmaf(fmaxf(w, 0.f), h, -g4));
        }
    }

    float stc = 0.f, strl = 0.f, cnt = 0.f;

    // classify: negatives inline, candidates to the queue
    if (a < A) {
        if (M4 < C4 * areaA) {
            float sig = 1.f / (1.f + __expf(-xl));
            stc = 0.75f * softplusf(xl) * sig * sig;        // focal, t=0
        } else if (M4 >= 0.3330f * areaA) {
            s_q[atomicAdd(&s_qc, 1)] = a;
        }
        // else: exact-iou in [0.4, 0.5) ignore band — contributes nothing
    }
    __syncthreads();

    // ---- pass-2: exact classification + argmax for candidates (dense) ----
    const int qc = s_qc;
    for (int i = threadIdx.x; i < qc; i += TPB) {
        const int aq = s_q[i];
        const float4 aw = reinterpret_cast<const float4*>(anchors)[aq];
        const float qx1 = aw.x, qy1 = aw.y;
        const float qx2 = aw.x + aw.z, qy2 = aw.y + aw.w;
        const float qar = aw.z * aw.w;

        // division-free exact argmax (strict > keeps first max) — verified
        // path (rel_err 6.6e-8 vs reference)
        float bI = 0.f, bS = 1.f; int bK = 0;
        for (int k = 0; k < K; k++) {
            float4 g = s_g[k];
            float w = fminf(qx2, g.z) - fmaxf(qx1, g.x);
            float h = fminf(qy2, g.w) - fmaxf(qy1, g.y);
            float inter = fmaxf(w, 0.f) * h;
            float S = qar + s_ga[k];
            bool cc = inter * bS > bI * S;
            bI = cc ? inter : bI;
            bS = cc ? S : bS;
            bK = cc ? k : bK;
        }
        const float ts = bI / (bS - bI);

        const float* p = prop + ((size_t)b * A + aq) * 6;
        const float x = p[4];
        const float sig = 1.f / (1.f + __expf(-x));
        if (ts >= 0.5f) {
            cnt += 1.f;
            float om = 1.f - sig;
            stc += 0.25f * softplusf(-x) * om * om;         // focal, t=1
            float2 q01 = *reinterpret_cast<const float2*>(p);
            float2 q23 = *reinterpret_cast<const float2*>(p + 2);
            float4 g = s_g[bK];
            float ew = fmaxf(fminf(q01.x + q23.x, g.z) - fmaxf(q01.x, g.x), 0.f);
            float eh = fmaxf(fminf(q01.y + q23.y, g.w) - fmaxf(q01.y, g.y), 0.f);
            float ei = ew * eh;
            float eiou = ei / ((q23.x * q23.y + s_ga[bK]) - ei);
            strl += -__logf(eiou + 0.01f);
        } else if (ts < 0.4f) {
            stc += 0.75f * softplusf(x) * sig * sig;        // focal, t=0
        }
    }

    // ---- block reduction of (stc, strl, cnt) ----
    const unsigned m = 0xFFFFFFFFu;
#pragma unroll
    for (int o = 16; o; o >>= 1) {
        stc  += __shfl_down_sync(m, stc,  o);
        strl += __shfl_down_sync(m, strl, o);
        cnt  += __shfl_down_sync(m, cnt,  o);
    }
    const int wid = threadIdx.x >> 5, lane = threadIdx.x & 31;
    if (lane == 0) { r0[wid] = stc; r1[wid] = strl; r2[wid] = cnt; }
    __syncthreads();
    if (threadIdx.x == 0) {
        float t0 = 0.f, t1 = 0.f, t2 = 0.f;
#pragma unroll
        for (int i = 0; i < TPB / 32; i++) { t0 += r0[i]; t1 += r1[i]; t2 += r2[i]; }
        int slot = (b * gx + blockIdx.x) * 4;
        g_part[slot + 0] = t0;
        g_part[slot + 1] = t1;
        g_part[slot + 2] = t2;
        __threadfence();
        unsigned old = atomicInc(&g_ctr, (unsigned)(totalBlocks - 1));
        s_last = (old == (unsigned)(totalBlocks - 1)) ? 1 : 0;
    }
    __syncthreads();

    if (s_last) {
        const int B = gridDim.y;
        const int nwarp = TPB / 32;
        if (threadIdx.x < 32) ((float*)s_fin)[threadIdx.x] = 0.f;
        __syncthreads();

        if (B <= nwarp) {
            const int wpb = nwarp / B;            // warps per batch
            const int bb = wid / wpb;
            if (bb < B) {
                float f0 = 0.f, f1 = 0.f, f2 = 0.f;
                for (int blk = lane + 32 * (wid % wpb); blk < gx; blk += 32 * wpb) {
                    int s = (bb * gx + blk) * 4;
                    f0 += g_part[s + 0];
                    f1 += g_part[s + 1];
                    f2 += g_part[s + 2];
                }
#pragma unroll
                for (int o = 16; o; o >>= 1) {
                    f0 += __shfl_down_sync(m, f0, o);
                    f1 += __shfl_down_sync(m, f1, o);
                    f2 += __shfl_down_sync(m, f2, o);
                }
                if (lane == 0) {
                    atomicAdd(&s_fin[bb][0], f0);
                    atomicAdd(&s_fin[bb][1], f1);
                    atomicAdd(&s_fin[bb][2], f2);
                }
            }
            __syncthreads();
            if (threadIdx.x == 0) {
                float t = 0.f;
                for (int bb2 = 0; bb2 < B; bb2++) {
                    float cc = s_fin[bb2][2];
                    float safe = (cc > 0.f) ? cc : 1.f;
                    t += s_fin[bb2][0] / safe;
                    if (cc > 0.f) t += s_fin[bb2][1] / safe;
                }
                out[0] = t / (float)B;
            }
        } else if (threadIdx.x == 0) {
            // fallback (B > nwarp): serial, correctness only
            float t = 0.f;
            for (int bb2 = 0; bb2 < B; bb2++) {
                float f0 = 0.f, f1 = 0.f, f2 = 0.f;
                for (int blk = 0; blk < gx; blk++) {
                    int s = (bb2 * gx + blk) * 4;
                    f0 += g_part[s]; f1 += g_part[s + 1]; f2 += g_part[s + 2];
                }
                float safe = (f2 > 0.f) ? f2 : 1.f;
                t += f0 / safe;
                if (f2 > 0.f) t += f1 / safe;
            }
            out[0] = t / (float)B;
        }
    }
}

extern "C" void kernel_launch(void* const* d_in, const int* in_sizes, int n_in,
                              void* d_out, int out_size) {
    const float* prop    = (const float*)d_in[0];  // ss_proposal (B,A,6)
    const float* anchors = (const float*)d_in[1];  // anchors (A,4)
    const float* gt      = (const float*)d_in[2];  // ground_truth (B,K,4)

    const int A = in_sizes[1] / 4;
    const int B = in_sizes[0] / (A * 6);
    const int K = in_sizes[2] / (B * 4);

    const int gx = (A + TPB - 1) / TPB;     // 469 for A=120000
    dim3 grid(gx, B);
    const int total = gx * B;

    if (K == 64)
        loss_kernel<64><<<grid, TPB>>>(prop, anchors, gt, (float*)d_out, A, K, total);
    else
        loss_kernel<0><<<grid, TPB>>>(prop, anchors, gt, (float*)d_out, A, K, total);
}